// round 10
// baseline (speedup 1.0000x reference)
#include <cuda_runtime.h>
#include <math.h>

#define LN2PI 1.8378770664093453f

// ---------------------------------------------------------------------------
// Device scratch
// ---------------------------------------------------------------------------
__device__ __align__(128) float g_fea[16 * 32 * 196];        // [b][c][s]
__device__ __align__(128) float g_M1[16 * 196 * 512];        // [b][s][u]  channel-fastest
__device__ __align__(128) float g_a1[16 * 196 * 32];         // [b][s][B]
__device__ __align__(128) float g_Mpatch[16 * 36 * 288 * 16];// [b][p][i][16]
__device__ __align__(128) float g_Apatch[16 * 36 * 288];     // [b][p][i]
__device__ __align__(128) float g_RT[16 * 1152 * 288];       // [b][j][i]
__device__ __align__(128) float g_miu2[16 * 1152 * 16];      // [bj][d]   (E-step layout)
__device__ __align__(128) float g_miuT2[16 * 36 * 16 * 32];  // [b][p][d][c] (L3 patch layout)
__device__ __align__(128) float g_aout2[16 * 1152];
__device__ __align__(128) float g_miu3[16 * 512 * 16];
__device__ __align__(128) float g_miuT3[16 * 16 * 16 * 32];  // [b][p][d][c] (L4 patch layout)
__device__ __align__(128) float g_aout3[16 * 512];
__device__ __align__(128) float g_miu4[16 * 5 * 16];
__device__ __align__(128) float g_aout4[16 * 5];
__device__ __align__(128) float g_isig[16 * 1152 * 16];
__device__ __align__(128) float g_lsum[16 * 1152];

// ---------------------------------------------------------------------------
// Stem conv 5x5 stride 2 + relu : (16,2,32,32) -> fea [b][o][s]
// ---------------------------------------------------------------------------
__global__ void k_stem(const float* __restrict__ x,
                       const float* __restrict__ cw,
                       const float* __restrict__ cb) {
    int idx = blockIdx.x * blockDim.x + threadIdx.x;
    if (idx >= 16 * 32 * 196) return;
    int xx = idx % 14;
    int y  = (idx / 14) % 14;
    int o  = (idx / 196) % 32;
    int b  = idx / (196 * 32);
    float acc = cb[o];
    #pragma unroll
    for (int ci = 0; ci < 2; ci++)
        #pragma unroll
        for (int ky = 0; ky < 5; ky++)
            #pragma unroll
            for (int kx = 0; kx < 5; kx++)
                acc = fmaf(x[((b * 2 + ci) * 32 + 2 * y + ky) * 32 + 2 * xx + kx],
                           cw[((o * 2 + ci) * 5 + ky) * 5 + kx], acc);
    g_fea[idx] = fmaxf(acc, 0.0f);
}

// ---------------------------------------------------------------------------
// Primary caps -> channel-fastest M1[b][s][u], a1[b][s][B]
// o fastest across threads so writes are coalesced; fea reads broadcast.
// ---------------------------------------------------------------------------
__global__ void k_primary(const float* __restrict__ pw, const float* __restrict__ pb,
                          const float* __restrict__ aw, const float* __restrict__ ab) {
    int idx = blockIdx.x * blockDim.x + threadIdx.x;
    if (idx >= 16 * 544 * 196) return;
    int o = idx % 544;
    int s = (idx / 544) % 196;
    int b = idx / (544 * 196);
    const float* f = &g_fea[(b * 32) * 196 + s];
    if (o < 512) {
        float acc = pb[o];
        #pragma unroll
        for (int c = 0; c < 32; c++) acc = fmaf(f[c * 196], pw[o * 32 + c], acc);
        g_M1[(b * 196 + s) * 512 + o] = acc;
    } else {
        int oa = o - 512;
        float acc = ab[oa];
        #pragma unroll
        for (int c = 0; c < 32; c++) acc = fmaf(f[c * 196], aw[oa * 32 + c], acc);
        g_a1[(b * 196 + s) * 32 + oa] = 1.0f / (1.0f + expf(-acc));
    }
}

// ---------------------------------------------------------------------------
// Per-layer config traits
// ---------------------------------------------------------------------------
template <int L> struct Cfg;

template <> struct Cfg<2> {
    static constexpr int C = 32, K = 3, S = 2, OW = 6;
    static constexpr int KK = 9, NI = 288, NJ = 1152, OHW = 36;
    __device__ static float Min(int b, int u, int y, int x) {
        return g_M1[(b * 196 + y * 14 + x) * 512 + u];     // contiguous over u
    }
    __device__ static float Ain(int b, int B_, int y, int x) {
        return g_a1[(b * 196 + y * 14 + x) * 32 + B_];
    }
    __device__ static float* miu()  { return g_miu2; }
    __device__ static float* miuT() { return g_miuT2; }
    __device__ static float* aout() { return g_aout2; }
};
template <> struct Cfg<3> {
    static constexpr int C = 32, K = 3, S = 1, OW = 4;
    static constexpr int KK = 9, NI = 288, NJ = 512, OHW = 16;
    // channel u -> (cp = u&31, dp = u>>5); read L2's transposed miu [b][s][dp][cp]
    __device__ static float Min(int b, int u, int y, int x) {
        int cp = u & 31, dp = u >> 5;
        return g_miuT2[((b * 36 + y * 6 + x) * 16 + dp) * 32 + cp];
    }
    __device__ static float Ain(int b, int B_, int y, int x) {
        return g_aout2[b * 1152 + B_ * 36 + y * 6 + x];
    }
    __device__ static float* miu()  { return g_miu3; }
    __device__ static float* miuT() { return g_miuT3; }
    __device__ static float* aout() { return g_aout3; }
};
template <> struct Cfg<4> {
    static constexpr int C = 5, K = 4, S = 1, OW = 1;
    static constexpr int KK = 16, NI = 512, NJ = 5, OHW = 1;
    __device__ static float Min(int b, int u, int y, int x) {
        int cp = u & 31, dp = u >> 5;
        return g_miuT3[((b * 16 + y * 4 + x) * 16 + dp) * 32 + cp];
    }
    __device__ static float Ain(int b, int B_, int y, int x) {
        return g_aout3[b * 512 + B_ * 16 + y * 4 + x];
    }
    __device__ static float* miu()  { return g_miu4; }
    __device__ static float* miuT() { return g_miuT3; } // unused
    __device__ static float* aout() { return g_aout4; }
};

// ---------------------------------------------------------------------------
// Fused patch builder: Mpatch[b][p][i][16] + Apatch[b][p][i] in one kernel
// ---------------------------------------------------------------------------
template <int L>
__global__ void k_patch() {
    using G = Cfg<L>;
    int idx = blockIdx.x * blockDim.x + threadIdx.x;
    const int total = 16 * G::OHW * G::NI * 16;
    if (idx >= total) return;
    int d  = idx & 15;
    int t  = idx >> 4;
    int i  = t % G::NI;
    int p  = (t / G::NI) % G::OHW;
    int b  = t / (G::NI * G::OHW);
    int B_ = i / G::KK, kk = i % G::KK;
    int y  = kk / G::K + G::S * (p / G::OW);
    int x  = kk % G::K + G::S * (p % G::OW);
    g_Mpatch[idx] = G::Min(b, B_ * 16 + d, y, x);
    if (d == 0) g_Apatch[t] = G::Ain(b, B_, y, x);
}

// ---------------------------------------------------------------------------
// Tiled M-step (L2/L3): one block per (b, 4c x 4p) tile of 16 j's.
// tid = js*16 + islot; compile-time trip count + unroll for MLP.
// Epilogue writes miu (E-step layout) AND miuT (next-layer patch layout).
// ---------------------------------------------------------------------------
template <int L>
__global__ void __launch_bounds__(256) k_mstep_t(const float* __restrict__ beta_a,
                                                 const float* __restrict__ beta_u,
                                                 const float* __restrict__ Wt,
                                                 float lam, int first) {
    using G = Cfg<L>;
    constexpr int PG = G::OHW / 4;
    int blk  = blockIdx.x;
    int pgrp = blk % PG;
    int cgrp = (blk / PG) % (G::C / 4);
    int b    = blk / (PG * (G::C / 4));
    int tid  = threadIdx.x;
    int js   = tid >> 4;
    int islot = tid & 15;
    int cg = js >> 2, pgg = js & 3;
    int c = cgrp * 4 + cg;
    int p = pgrp * 4 + pgg;
    int j = c * G::OHW + p;

    const float invNJ = 1.0f / (float)G::NJ;
    float accS = 0.0f, accM[16], accQ[16];
    #pragma unroll
    for (int d = 0; d < 16; d++) { accM[d] = 0.0f; accQ[d] = 0.0f; }

    const float* Rrow = g_RT + ((size_t)(b * G::NJ + j)) * G::NI;
    const float* Arow = g_Apatch + (size_t)(b * G::OHW + p) * G::NI;
    const float* Mrow = g_Mpatch + (size_t)(b * G::OHW + p) * G::NI * 16;

    #pragma unroll 2
    for (int it = 0; it < G::NI / 16; it++) {
        int i = it * 16 + islot;
        int B_ = i / G::KK, kk = i % G::KK;
        float r  = first ? invNJ : Rrow[i];
        float ra = r * Arow[i];
        const float4* Mp4 = reinterpret_cast<const float4*>(Mrow + (size_t)i * 16);
        const float4* W4 = reinterpret_cast<const float4*>(
            Wt + ((B_ * G::KK + kk) * G::C + c) * 16);
        float Mv[16], Wv[16];
        #pragma unroll
        for (int q4 = 0; q4 < 4; q4++) {
            float4 m = Mp4[q4], w = W4[q4];
            Mv[q4 * 4 + 0] = m.x; Mv[q4 * 4 + 1] = m.y; Mv[q4 * 4 + 2] = m.z; Mv[q4 * 4 + 3] = m.w;
            Wv[q4 * 4 + 0] = w.x; Wv[q4 * 4 + 1] = w.y; Wv[q4 * 4 + 2] = w.z; Wv[q4 * 4 + 3] = w.w;
        }
        accS += ra;
        #pragma unroll
        for (int r0 = 0; r0 < 4; r0++)
            #pragma unroll
            for (int cc = 0; cc < 4; cc++) {
                float v = 0.0f;
                #pragma unroll
                for (int t = 0; t < 4; t++) v = fmaf(Wv[r0 * 4 + t], Mv[t * 4 + cc], v);
                int e = r0 * 4 + cc;
                accM[e] = fmaf(ra, v, accM[e]);
                accQ[e] = fmaf(ra * v, v, accQ[e]);
            }
    }

    #pragma unroll
    for (int off = 8; off; off >>= 1) {
        accS += __shfl_down_sync(0xffffffffu, accS, off, 16);
        #pragma unroll
        for (int d = 0; d < 16; d++) {
            accM[d] += __shfl_down_sync(0xffffffffu, accM[d], off, 16);
            accQ[d] += __shfl_down_sync(0xffffffffu, accQ[d], off, 16);
        }
    }
    __shared__ float tot[16][33];
    if (islot == 0) {
        #pragma unroll
        for (int d = 0; d < 16; d++) { tot[js][d] = accM[d]; tot[js][16 + d] = accQ[d]; }
        tot[js][32] = accS;
    }
    __syncthreads();
    {
        int js2 = tid >> 4, d = tid & 15;
        int c2 = cgrp * 4 + (js2 >> 2);
        int p2 = pgrp * 4 + (js2 & 3);
        int j2 = c2 * G::OHW + p2;
        int bj = b * G::NJ + j2;
        float coeff = fmaxf(tot[js2][32], 1e-8f);
        float q     = tot[js2][32] / coeff;
        float mi    = tot[js2][d] / coeff;
        float sg    = fmaxf(tot[js2][16 + d] / coeff - (2.0f - q) * mi * mi, 1e-8f);
        Cfg<L>::miu()[bj * 16 + d] = mi;
        Cfg<L>::miuT()[((b * G::OHW + p2) * 16 + d) * 32 + c2] = mi;
        g_isig[bj * 16 + d] = 1.0f / sg;
        float ls = logf(sg);
        #pragma unroll
        for (int off = 8; off; off >>= 1) ls += __shfl_down_sync(0xffffffffu, ls, off, 16);
        if (d == 0) {
            g_lsum[bj] = ls;
            int jc = j2 % G::C;
            float cost = coeff * (16.0f * beta_u[jc] + 0.5f * ls);
            float z = lam * (beta_a[jc] - cost);
            Cfg<L>::aout()[bj] = 1.0f / (1.0f + expf(-z));
        }
    }
}

// ---------------------------------------------------------------------------
// L4 M-step (NJ=5, shared W, coords). One block per (b,j).
// ---------------------------------------------------------------------------
__global__ void __launch_bounds__(128) k_mstep4(const float* __restrict__ beta_a,
                                                const float* __restrict__ beta_u,
                                                const float* __restrict__ Wt,
                                                float lam, int first) {
    int bj = blockIdx.x;
    int j  = bj % 5;
    int b  = bj / 5;
    int tid = threadIdx.x;

    float accS = 0.0f, accM[16], accQ[16];
    #pragma unroll
    for (int d = 0; d < 16; d++) { accM[d] = 0.0f; accQ[d] = 0.0f; }

    #pragma unroll 2
    for (int it = 0; it < 4; it++) {
        int i = it * 128 + tid;
        int B_ = i >> 4, kk = i & 15;
        float r  = first ? 0.2f : g_RT[(b * 5 + j) * 512 + i];
        float ra = r * g_Apatch[b * 512 + i];
        const float4* Mp4 = reinterpret_cast<const float4*>(g_Mpatch + ((size_t)(b * 512 + i)) * 16);
        const float4* W4  = reinterpret_cast<const float4*>(Wt + (B_ * 5 + j) * 16);
        float Mv[16], Wv[16];
        #pragma unroll
        for (int q4 = 0; q4 < 4; q4++) {
            float4 m = Mp4[q4], w = W4[q4];
            Mv[q4 * 4 + 0] = m.x; Mv[q4 * 4 + 1] = m.y; Mv[q4 * 4 + 2] = m.z; Mv[q4 * 4 + 3] = m.w;
            Wv[q4 * 4 + 0] = w.x; Wv[q4 * 4 + 1] = w.y; Wv[q4 * 4 + 2] = w.z; Wv[q4 * 4 + 3] = w.w;
        }
        float cx = (float)(kk >> 2) * 0.25f;
        float cy = (float)(kk & 3) * 0.25f;
        accS += ra;
        #pragma unroll
        for (int r0 = 0; r0 < 4; r0++)
            #pragma unroll
            for (int cc = 0; cc < 4; cc++) {
                float v = 0.0f;
                #pragma unroll
                for (int t = 0; t < 4; t++) v = fmaf(Wv[r0 * 4 + t], Mv[t * 4 + cc], v);
                int e = r0 * 4 + cc;
                if (e == 0) v += cx;
                if (e == 1) v += cy;
                accM[e] = fmaf(ra, v, accM[e]);
                accQ[e] = fmaf(ra * v, v, accQ[e]);
            }
    }

    __shared__ float red[33][4];
    __shared__ float tot[33];
    #pragma unroll
    for (int off = 16; off; off >>= 1) {
        accS += __shfl_down_sync(0xffffffffu, accS, off);
        #pragma unroll
        for (int d = 0; d < 16; d++) {
            accM[d] += __shfl_down_sync(0xffffffffu, accM[d], off);
            accQ[d] += __shfl_down_sync(0xffffffffu, accQ[d], off);
        }
    }
    int w = tid >> 5;
    if ((tid & 31) == 0) {
        #pragma unroll
        for (int d = 0; d < 16; d++) { red[d][w] = accM[d]; red[16 + d][w] = accQ[d]; }
        red[32][w] = accS;
    }
    __syncthreads();
    if (tid < 33) {
        float t = 0.0f;
        #pragma unroll
        for (int q = 0; q < 4; q++) t += red[tid][q];
        tot[tid] = t;
    }
    __syncthreads();
    if (tid < 16) {
        float coeff = fmaxf(tot[32], 1e-8f);
        float q     = tot[32] / coeff;
        float mi    = tot[tid] / coeff;
        float sg    = fmaxf(tot[16 + tid] / coeff - (2.0f - q) * mi * mi, 1e-8f);
        g_miu4[bj * 16 + tid] = mi;
        g_isig[bj * 16 + tid] = 1.0f / sg;
        float ls = logf(sg);
        #pragma unroll
        for (int off = 8; off; off >>= 1) ls += __shfl_down_sync(0x0000ffffu, ls, off, 16);
        if (tid == 0) {
            g_lsum[bj] = ls;
            float cost = coeff * (16.0f * beta_u[j] + 0.5f * ls);
            float z = lam * (beta_a[j] - cost);
            g_aout4[bj] = 1.0f / (1.0f + expf(-z));
        }
    }
}

// ---------------------------------------------------------------------------
// Tiled E-step (L2/L3): one block per (b, B_), covering all KK kk's.
// ---------------------------------------------------------------------------
template <int L>
__global__ void __launch_bounds__(256) k_estep_t(const float* __restrict__ Wt) {
    using G = Cfg<L>;
    extern __shared__ float sm[];
    float* s   = sm;
    float* sMp = sm + G::KK * G::NJ;
    float* sW  = sMp + G::KK * G::OHW * 17;

    int blk = blockIdx.x;
    int B_  = blk & 31;
    int b   = blk >> 5;
    int tid = threadIdx.x;

    for (int idx = tid; idx < G::KK * G::OHW * 16; idx += 256) {
        int d  = idx & 15;
        int p  = (idx >> 4) % G::OHW;
        int kk = idx / (16 * G::OHW);
        sMp[(kk * G::OHW + p) * 17 + d] =
            g_Mpatch[((size_t)(b * G::OHW + p) * G::NI + B_ * G::KK + kk) * 16 + d];
    }
    for (int idx = tid; idx < G::KK * G::C * 16; idx += 256) {
        int d  = idx & 15;
        int c  = (idx >> 4) % G::C;
        int kk = idx / (16 * G::C);
        sW[(kk * G::C + c) * 17 + d] = Wt[((B_ * G::KK + kk) * G::C + c) * 16 + d];
    }
    __syncthreads();

    const float* miu  = Cfg<L>::miu();
    const float* aout = Cfg<L>::aout();
    float lmax[G::KK];
    #pragma unroll
    for (int kk = 0; kk < G::KK; kk++) lmax[kk] = -3.0e38f;

    for (int j = tid; j < G::NJ; j += 256) {
        int c = j / G::OHW, p = j % G::OHW;
        int bj = b * G::NJ + j;
        float mu[16], iv[16];
        const float4* mp4 = reinterpret_cast<const float4*>(miu + bj * 16);
        const float4* ip4 = reinterpret_cast<const float4*>(g_isig + bj * 16);
        #pragma unroll
        for (int q4 = 0; q4 < 4; q4++) {
            float4 m = mp4[q4], v = ip4[q4];
            mu[q4 * 4 + 0] = m.x; mu[q4 * 4 + 1] = m.y; mu[q4 * 4 + 2] = m.z; mu[q4 * 4 + 3] = m.w;
            iv[q4 * 4 + 0] = v.x; iv[q4 * 4 + 1] = v.y; iv[q4 * 4 + 2] = v.z; iv[q4 * 4 + 3] = v.w;
        }
        float base = g_lsum[bj] + 16.0f * LN2PI;
        float aj   = aout[bj];
        #pragma unroll
        for (int kk = 0; kk < G::KK; kk++) {
            const float* Wp = sW + (kk * G::C + c) * 17;
            const float* Mp = sMp + (kk * G::OHW + p) * 17;
            float acc = base;
            #pragma unroll
            for (int r0 = 0; r0 < 4; r0++)
                #pragma unroll
                for (int cc = 0; cc < 4; cc++) {
                    float v = 0.0f;
                    #pragma unroll
                    for (int t = 0; t < 4; t++) v = fmaf(Wp[r0 * 4 + t], Mp[t * 4 + cc], v);
                    int e = r0 * 4 + cc;
                    float dd = v - mu[e];
                    acc = fmaf(dd * dd, iv[e], acc);
                }
            float sj = aj * (-0.5f * acc);
            s[kk * G::NJ + j] = sj;
            lmax[kk] = fmaxf(lmax[kk], sj);
        }
    }

    __shared__ float redm[G::KK][8];
    __shared__ float reds[G::KK][8];
    #pragma unroll
    for (int kk = 0; kk < G::KK; kk++)
        #pragma unroll
        for (int off = 16; off; off >>= 1)
            lmax[kk] = fmaxf(lmax[kk], __shfl_down_sync(0xffffffffu, lmax[kk], off));
    int w = tid >> 5;
    if ((tid & 31) == 0)
        #pragma unroll
        for (int kk = 0; kk < G::KK; kk++) redm[kk][w] = lmax[kk];
    __syncthreads();
    float m[G::KK];
    #pragma unroll
    for (int kk = 0; kk < G::KK; kk++) {
        float mm = redm[kk][0];
        #pragma unroll
        for (int q = 1; q < 8; q++) mm = fmaxf(mm, redm[kk][q]);
        m[kk] = mm;
    }

    float lsm[G::KK];
    #pragma unroll
    for (int kk = 0; kk < G::KK; kk++) lsm[kk] = 0.0f;
    for (int j = tid; j < G::NJ; j += 256) {
        #pragma unroll
        for (int kk = 0; kk < G::KK; kk++) {
            float e = expf(s[kk * G::NJ + j] - m[kk]);
            s[kk * G::NJ + j] = e;
            lsm[kk] += e;
        }
    }
    #pragma unroll
    for (int kk = 0; kk < G::KK; kk++)
        #pragma unroll
        for (int off = 16; off; off >>= 1)
            lsm[kk] += __shfl_down_sync(0xffffffffu, lsm[kk], off);
    if ((tid & 31) == 0)
        #pragma unroll
        for (int kk = 0; kk < G::KK; kk++) reds[kk][w] = lsm[kk];
    __syncthreads();
    float inv[G::KK];
    #pragma unroll
    for (int kk = 0; kk < G::KK; kk++) {
        float t = 0.0f;
        #pragma unroll
        for (int q = 0; q < 8; q++) t += reds[kk][q];
        inv[kk] = 1.0f / t;
    }

    for (int j = tid; j < G::NJ; j += 256) {
        float* dst = &g_RT[((size_t)(b * G::NJ + j)) * G::NI + B_ * G::KK];
        #pragma unroll
        for (int kk = 0; kk < G::KK; kk++) dst[kk] = s[kk * G::NJ + j] * inv[kk];
    }
}

// ---------------------------------------------------------------------------
// E-step L4: one warp per (b,i)
// ---------------------------------------------------------------------------
__global__ void __launch_bounds__(256) k_estep4(const float* __restrict__ Wt) {
    int g    = blockIdx.x * 8 + (threadIdx.x >> 5);
    int lane = threadIdx.x & 31;
    int i = g & 511;
    int b = g >> 9;
    int B_ = i >> 4, kk = i & 15;

    float Mv[16];
    const float4* Mp4 = reinterpret_cast<const float4*>(g_Mpatch + ((size_t)(b * 512 + i)) * 16);
    #pragma unroll
    for (int q4 = 0; q4 < 4; q4++) {
        float4 mv = Mp4[q4];
        Mv[q4 * 4 + 0] = mv.x; Mv[q4 * 4 + 1] = mv.y; Mv[q4 * 4 + 2] = mv.z; Mv[q4 * 4 + 3] = mv.w;
    }
    float cx = (float)(kk >> 2) * 0.25f;
    float cy = (float)(kk & 3) * 0.25f;

    float sj = -3.0e38f;
    if (lane < 5) {
        int bj = b * 5 + lane;
        const float4* W4 = reinterpret_cast<const float4*>(Wt + (B_ * 5 + lane) * 16);
        float Wv[16];
        #pragma unroll
        for (int q4 = 0; q4 < 4; q4++) {
            float4 wv = W4[q4];
            Wv[q4 * 4 + 0] = wv.x; Wv[q4 * 4 + 1] = wv.y; Wv[q4 * 4 + 2] = wv.z; Wv[q4 * 4 + 3] = wv.w;
        }
        const float* mu = g_miu4 + bj * 16;
        const float* iv = g_isig + bj * 16;
        float acc = g_lsum[bj] + 16.0f * LN2PI;
        #pragma unroll
        for (int r0 = 0; r0 < 4; r0++)
            #pragma unroll
            for (int cc = 0; cc < 4; cc++) {
                float v = 0.0f;
                #pragma unroll
                for (int t = 0; t < 4; t++) v = fmaf(Wv[r0 * 4 + t], Mv[t * 4 + cc], v);
                int e = r0 * 4 + cc;
                if (e == 0) v += cx;
                if (e == 1) v += cy;
                float dd = v - mu[e];
                acc = fmaf(dd * dd, iv[e], acc);
            }
        sj = g_aout4[bj] * (-0.5f * acc);
    }
    float mm = sj;
    #pragma unroll
    for (int off = 16; off; off >>= 1) mm = fmaxf(mm, __shfl_xor_sync(0xffffffffu, mm, off));
    float e = (lane < 5) ? expf(sj - mm) : 0.0f;
    float ssum = e;
    #pragma unroll
    for (int off = 16; off; off >>= 1) ssum += __shfl_xor_sync(0xffffffffu, ssum, off);
    if (lane < 5) g_RT[(b * 5 + lane) * 512 + i] = e / ssum;
}

__global__ void k_final(float* __restrict__ out) {
    int idx = threadIdx.x;
    if (idx < 80) out[idx] = g_aout4[idx];
}

// ---------------------------------------------------------------------------
// Host. Launch order puts k_mstep_t<2> at global launch #4 so the fixed
// ncu window (-s/-c) captures the dominant kernel.
// ---------------------------------------------------------------------------
template <int L>
static void run_layer(const float* W, const float* ba, const float* bu) {
    using G = Cfg<L>;
    const int esmem = (G::KK * G::NJ + G::KK * G::OHW * 17 + G::KK * G::C * 17) * 4;
    cudaFuncSetAttribute(k_estep_t<L>, cudaFuncAttributeMaxDynamicSharedMemorySize, esmem);

    k_patch<L><<<(16 * G::OHW * G::NI * 16 + 255) / 256, 256>>>();
    for (int t = 0; t < 3; t++) {
        float lam = 0.01f * (1.0f - powf(0.95f, (float)(t + 1)));
        k_mstep_t<L><<<16 * (G::C / 4) * (G::OHW / 4), 256>>>(ba, bu, W, lam, t == 0 ? 1 : 0);
        if (t < 2) k_estep_t<L><<<16 * 32, 256, esmem>>>(W);
    }
}

static void run_layer4(const float* W, const float* ba, const float* bu) {
    k_patch<4><<<(16 * 512 * 16 + 255) / 256, 256>>>();
    for (int t = 0; t < 3; t++) {
        float lam = 0.01f * (1.0f - powf(0.95f, (float)(t + 1)));
        k_mstep4<<<16 * 5, 128>>>(ba, bu, W, lam, t == 0 ? 1 : 0);
        if (t < 2) k_estep4<<<16 * 512 / 8, 256>>>(W);
    }
}

extern "C" void kernel_launch(void* const* d_in, const int* in_sizes, int n_in,
                              void* d_out, int out_size) {
    const float* x      = (const float*)d_in[0];
    const float* conv_w = (const float*)d_in[1];
    const float* conv_b = (const float*)d_in[2];
    const float* pose_w = (const float*)d_in[3];
    const float* pose_b = (const float*)d_in[4];
    const float* act_w  = (const float*)d_in[5];
    const float* act_b  = (const float*)d_in[6];
    const float* W2     = (const float*)d_in[7];
    const float* ba2    = (const float*)d_in[8];
    const float* bu2    = (const float*)d_in[9];
    const float* W3     = (const float*)d_in[10];
    const float* ba3    = (const float*)d_in[11];
    const float* bu3    = (const float*)d_in[12];
    const float* W4     = (const float*)d_in[13];
    const float* ba4    = (const float*)d_in[14];
    const float* bu4    = (const float*)d_in[15];

    // launch #1..#3: stem, primary, patch<2>   -> launch #4 = k_mstep_t<2>
    k_stem<<<(16 * 32 * 196 + 255) / 256, 256>>>(x, conv_w, conv_b);
    k_primary<<<(16 * 544 * 196 + 255) / 256, 256>>>(pose_w, pose_b, act_w, act_b);

    run_layer<2>(W2, ba2, bu2);
    run_layer<3>(W3, ba3, bu3);
    run_layer4(W4, ba4, bu4);

    k_final<<<1, 128>>>((float*)d_out);
}

// round 12
// speedup vs baseline: 1.7261x; 1.7261x over previous
#include <cuda_runtime.h>
#include <math.h>

#define LN2PI 1.8378770664093453f

// ---------------------------------------------------------------------------
// Device scratch
// ---------------------------------------------------------------------------
__device__ __align__(128) float g_fea[16 * 32 * 196];        // [b][c][s]
__device__ __align__(128) float g_M1[16 * 196 * 512];        // [b][s][u]  channel-fastest
__device__ __align__(128) float g_a1[16 * 196 * 32];         // [b][s][B]
__device__ __align__(128) float g_Mpatch[16 * 36 * 288 * 16];// [b][p][i][16]
__device__ __align__(128) float g_Apatch[16 * 36 * 288];     // [b][p][i]
__device__ __align__(128) float g_R[16 * 288 * 1152];        // [b][i][j]  natural order
__device__ __align__(128) float g_miu2[16 * 1152 * 16];      // [bj][d]   (E-step layout)
__device__ __align__(128) float g_miuT2[16 * 36 * 16 * 32];  // [b][p][d][c] (L3 patch layout)
__device__ __align__(128) float g_aout2[16 * 1152];
__device__ __align__(128) float g_miu3[16 * 512 * 16];
__device__ __align__(128) float g_miuT3[16 * 16 * 16 * 32];  // [b][p][d][c] (L4 patch layout)
__device__ __align__(128) float g_aout3[16 * 512];
__device__ __align__(128) float g_miu4[16 * 5 * 16];
__device__ __align__(128) float g_aout4[16 * 5];
__device__ __align__(128) float g_isig[16 * 1152 * 16];
__device__ __align__(128) float g_lsum[16 * 1152];

// ---------------------------------------------------------------------------
// Stem conv 5x5 stride 2 + relu : (16,2,32,32) -> fea [b][o][s]
// ---------------------------------------------------------------------------
__global__ void k_stem(const float* __restrict__ x,
                       const float* __restrict__ cw,
                       const float* __restrict__ cb) {
    int idx = blockIdx.x * blockDim.x + threadIdx.x;
    if (idx >= 16 * 32 * 196) return;
    int xx = idx % 14;
    int y  = (idx / 14) % 14;
    int o  = (idx / 196) % 32;
    int b  = idx / (196 * 32);
    float acc = cb[o];
    #pragma unroll
    for (int ci = 0; ci < 2; ci++)
        #pragma unroll
        for (int ky = 0; ky < 5; ky++)
            #pragma unroll
            for (int kx = 0; kx < 5; kx++)
                acc = fmaf(x[((b * 2 + ci) * 32 + 2 * y + ky) * 32 + 2 * xx + kx],
                           cw[((o * 2 + ci) * 5 + ky) * 5 + kx], acc);
    g_fea[idx] = fmaxf(acc, 0.0f);
}

// ---------------------------------------------------------------------------
// Primary caps. Lanes s-fast (coalesced fea reads, broadcast weights);
// stores to channel-fastest layouts are scattered but cheap (one per thread).
// ---------------------------------------------------------------------------
__global__ void k_primary(const float* __restrict__ pw, const float* __restrict__ pb,
                          const float* __restrict__ aw, const float* __restrict__ ab) {
    int idx = blockIdx.x * blockDim.x + threadIdx.x;
    if (idx >= 16 * 544 * 196) return;
    int s = idx % 196;
    int o = (idx / 196) % 544;
    int b = idx / (196 * 544);
    const float* f = &g_fea[(b * 32) * 196 + s];
    if (o < 512) {
        float acc = pb[o];
        #pragma unroll
        for (int c = 0; c < 32; c++) acc = fmaf(f[c * 196], pw[o * 32 + c], acc);
        g_M1[(b * 196 + s) * 512 + o] = acc;
    } else {
        int oa = o - 512;
        float acc = ab[oa];
        #pragma unroll
        for (int c = 0; c < 32; c++) acc = fmaf(f[c * 196], aw[oa * 32 + c], acc);
        g_a1[(b * 196 + s) * 32 + oa] = 1.0f / (1.0f + expf(-acc));
    }
}

// ---------------------------------------------------------------------------
// Per-layer config traits
// ---------------------------------------------------------------------------
template <int L> struct Cfg;

template <> struct Cfg<2> {
    static constexpr int C = 32, K = 3, S = 2, OW = 6;
    static constexpr int KK = 9, NI = 288, NJ = 1152, OHW = 36;
    __device__ static float Min(int b, int u, int y, int x) {
        return g_M1[(b * 196 + y * 14 + x) * 512 + u];     // contiguous over u
    }
    __device__ static float Ain(int b, int B_, int y, int x) {
        return g_a1[(b * 196 + y * 14 + x) * 32 + B_];
    }
    __device__ static float* miu()  { return g_miu2; }
    __device__ static float* miuT() { return g_miuT2; }
    __device__ static float* aout() { return g_aout2; }
};
template <> struct Cfg<3> {
    static constexpr int C = 32, K = 3, S = 1, OW = 4;
    static constexpr int KK = 9, NI = 288, NJ = 512, OHW = 16;
    __device__ static float Min(int b, int u, int y, int x) {
        int cp = u & 31, dp = u >> 5;
        return g_miuT2[((b * 36 + y * 6 + x) * 16 + dp) * 32 + cp];
    }
    __device__ static float Ain(int b, int B_, int y, int x) {
        return g_aout2[b * 1152 + B_ * 36 + y * 6 + x];
    }
    __device__ static float* miu()  { return g_miu3; }
    __device__ static float* miuT() { return g_miuT3; }
    __device__ static float* aout() { return g_aout3; }
};
template <> struct Cfg<4> {
    static constexpr int C = 5, K = 4, S = 1, OW = 1;
    static constexpr int KK = 16, NI = 512, NJ = 5, OHW = 1;
    __device__ static float Min(int b, int u, int y, int x) {
        int cp = u & 31, dp = u >> 5;
        return g_miuT3[((b * 16 + y * 4 + x) * 16 + dp) * 32 + cp];
    }
    __device__ static float Ain(int b, int B_, int y, int x) {
        return g_aout3[b * 512 + B_ * 16 + y * 4 + x];
    }
    __device__ static float* miu()  { return g_miu4; }
    __device__ static float* miuT() { return g_miuT3; } // unused
    __device__ static float* aout() { return g_aout4; }
};

// ---------------------------------------------------------------------------
// Fused patch builder: Mpatch[b][p][i][16] + Apatch[b][p][i]
// ---------------------------------------------------------------------------
template <int L>
__global__ void k_patch() {
    using G = Cfg<L>;
    int idx = blockIdx.x * blockDim.x + threadIdx.x;
    const int total = 16 * G::OHW * G::NI * 16;
    if (idx >= total) return;
    int d  = idx & 15;
    int t  = idx >> 4;
    int i  = t % G::NI;
    int p  = (t / G::NI) % G::OHW;
    int b  = t / (G::NI * G::OHW);
    int B_ = i / G::KK, kk = i % G::KK;
    int y  = kk / G::K + G::S * (p / G::OW);
    int x  = kk % G::K + G::S * (p % G::OW);
    g_Mpatch[idx] = G::Min(b, B_ * 16 + d, y, x);
    if (d == 0) g_Apatch[t] = G::Ain(b, B_, y, x);
}

// ---------------------------------------------------------------------------
// Tiled M-step (L2/L3): one block per (b, 4c x 4p) tile of 16 j's.
// TRANSPOSED lane map: islot = tid>>4, js = tid&15. Each 16-lane half-warp
// shares one i and spans all 16 js -> Mp addresses collapse to 4 unique rows
// (p in 4), W to 4 unique rows (c in 4): every warp LDG.128 touches 8x16B =
// 128B = 1 L1 wavefront (was 4). R stored [b][i][j]: same-i lanes read 4
// clusters of 4 consecutive floats.
// ---------------------------------------------------------------------------
template <int L>
__global__ void __launch_bounds__(256) k_mstep_t(const float* __restrict__ beta_a,
                                                 const float* __restrict__ beta_u,
                                                 const float* __restrict__ Wt,
                                                 float lam, int first) {
    using G = Cfg<L>;
    constexpr int PG = G::OHW / 4;
    int blk  = blockIdx.x;
    int pgrp = blk % PG;
    int cgrp = (blk / PG) % (G::C / 4);
    int b    = blk / (PG * (G::C / 4));
    int tid  = threadIdx.x;
    int islot = tid >> 4;       // i-slot: 2 per warp
    int js    = tid & 15;       // j-slot: 16 per half-warp
    int cg = js >> 2, pgg = js & 3;
    int c = cgrp * 4 + cg;
    int p = pgrp * 4 + pgg;
    int j = c * G::OHW + p;

    const float invNJ = 1.0f / (float)G::NJ;
    float accS = 0.0f, accM[16], accQ[16];
    #pragma unroll
    for (int d = 0; d < 16; d++) { accM[d] = 0.0f; accQ[d] = 0.0f; }

    const float* Arow = g_Apatch + (size_t)(b * G::OHW + p) * G::NI;
    const float* Mrow = g_Mpatch + (size_t)(b * G::OHW + p) * G::NI * 16;
    const float* Rb   = g_R + (size_t)b * G::NI * G::NJ;

    for (int it = 0; it < G::NI / 16; it++) {
        int i = it * 16 + islot;
        int B_ = i / G::KK, kk = i % G::KK;
        float r  = first ? invNJ : Rb[(size_t)i * G::NJ + j];
        float ra = r * Arow[i];
        const float4* Mp4 = reinterpret_cast<const float4*>(Mrow + (size_t)i * 16);
        const float4* W4 = reinterpret_cast<const float4*>(
            Wt + ((B_ * G::KK + kk) * G::C + c) * 16);
        float Mv[16], Wv[16];
        #pragma unroll
        for (int q4 = 0; q4 < 4; q4++) {
            float4 m = Mp4[q4], w = W4[q4];
            Mv[q4 * 4 + 0] = m.x; Mv[q4 * 4 + 1] = m.y; Mv[q4 * 4 + 2] = m.z; Mv[q4 * 4 + 3] = m.w;
            Wv[q4 * 4 + 0] = w.x; Wv[q4 * 4 + 1] = w.y; Wv[q4 * 4 + 2] = w.z; Wv[q4 * 4 + 3] = w.w;
        }
        accS += ra;
        #pragma unroll
        for (int r0 = 0; r0 < 4; r0++)
            #pragma unroll
            for (int cc = 0; cc < 4; cc++) {
                float v = 0.0f;
                #pragma unroll
                for (int t = 0; t < 4; t++) v = fmaf(Wv[r0 * 4 + t], Mv[t * 4 + cc], v);
                int e = r0 * 4 + cc;
                accM[e] = fmaf(ra, v, accM[e]);
                accQ[e] = fmaf(ra * v, v, accQ[e]);
            }
    }

    // combine the two islots within each warp (lane l += lane l+16)
    accS += __shfl_down_sync(0xffffffffu, accS, 16);
    #pragma unroll
    for (int d = 0; d < 16; d++) {
        accM[d] += __shfl_down_sync(0xffffffffu, accM[d], 16);
        accQ[d] += __shfl_down_sync(0xffffffffu, accQ[d], 16);
    }
    __shared__ float stot[8][16][33];
    int w = tid >> 5, lane = tid & 31;
    if (lane < 16) {
        #pragma unroll
        for (int d = 0; d < 16; d++) { stot[w][lane][d] = accM[d]; stot[w][lane][16 + d] = accQ[d]; }
        stot[w][lane][32] = accS;
    }
    __syncthreads();
    {
        int js2 = tid >> 4, d = tid & 15;
        float sm_ = 0.0f, sq_ = 0.0f, ss_ = 0.0f;
        #pragma unroll
        for (int q = 0; q < 8; q++) {
            sm_ += stot[q][js2][d];
            sq_ += stot[q][js2][16 + d];
            ss_ += stot[q][js2][32];
        }
        int c2 = cgrp * 4 + (js2 >> 2);
        int p2 = pgrp * 4 + (js2 & 3);
        int j2 = c2 * G::OHW + p2;
        int bj = b * G::NJ + j2;
        float coeff = fmaxf(ss_, 1e-8f);
        float q     = ss_ / coeff;
        float mi    = sm_ / coeff;
        float sg    = fmaxf(sq_ / coeff - (2.0f - q) * mi * mi, 1e-8f);
        Cfg<L>::miu()[bj * 16 + d] = mi;
        Cfg<L>::miuT()[((b * G::OHW + p2) * 16 + d) * 32 + c2] = mi;
        g_isig[bj * 16 + d] = 1.0f / sg;
        float ls = logf(sg);
        #pragma unroll
        for (int off = 8; off; off >>= 1) ls += __shfl_down_sync(0xffffffffu, ls, off, 16);
        if (d == 0) {
            g_lsum[bj] = ls;
            int jc = j2 % G::C;
            float cost = coeff * (16.0f * beta_u[jc] + 0.5f * ls);
            float z = lam * (beta_a[jc] - cost);
            Cfg<L>::aout()[bj] = 1.0f / (1.0f + expf(-z));
        }
    }
}

// ---------------------------------------------------------------------------
// L4 M-step (NJ=5, shared W, coords). One block per (b,j).
// ---------------------------------------------------------------------------
__global__ void __launch_bounds__(128) k_mstep4(const float* __restrict__ beta_a,
                                                const float* __restrict__ beta_u,
                                                const float* __restrict__ Wt,
                                                float lam, int first) {
    int bj = blockIdx.x;
    int j  = bj % 5;
    int b  = bj / 5;
    int tid = threadIdx.x;

    float accS = 0.0f, accM[16], accQ[16];
    #pragma unroll
    for (int d = 0; d < 16; d++) { accM[d] = 0.0f; accQ[d] = 0.0f; }

    for (int it = 0; it < 4; it++) {
        int i = it * 128 + tid;
        int B_ = i >> 4, kk = i & 15;
        float r  = first ? 0.2f : g_R[((size_t)(b * 512 + i)) * 5 + j];
        float ra = r * g_Apatch[b * 512 + i];
        const float4* Mp4 = reinterpret_cast<const float4*>(g_Mpatch + ((size_t)(b * 512 + i)) * 16);
        const float4* W4  = reinterpret_cast<const float4*>(Wt + (B_ * 5 + j) * 16);
        float Mv[16], Wv[16];
        #pragma unroll
        for (int q4 = 0; q4 < 4; q4++) {
            float4 m = Mp4[q4], w = W4[q4];
            Mv[q4 * 4 + 0] = m.x; Mv[q4 * 4 + 1] = m.y; Mv[q4 * 4 + 2] = m.z; Mv[q4 * 4 + 3] = m.w;
            Wv[q4 * 4 + 0] = w.x; Wv[q4 * 4 + 1] = w.y; Wv[q4 * 4 + 2] = w.z; Wv[q4 * 4 + 3] = w.w;
        }
        float cx = (float)(kk >> 2) * 0.25f;
        float cy = (float)(kk & 3) * 0.25f;
        accS += ra;
        #pragma unroll
        for (int r0 = 0; r0 < 4; r0++)
            #pragma unroll
            for (int cc = 0; cc < 4; cc++) {
                float v = 0.0f;
                #pragma unroll
                for (int t = 0; t < 4; t++) v = fmaf(Wv[r0 * 4 + t], Mv[t * 4 + cc], v);
                int e = r0 * 4 + cc;
                if (e == 0) v += cx;
                if (e == 1) v += cy;
                accM[e] = fmaf(ra, v, accM[e]);
                accQ[e] = fmaf(ra * v, v, accQ[e]);
            }
    }

    __shared__ float red[33][4];
    __shared__ float tot[33];
    #pragma unroll
    for (int off = 16; off; off >>= 1) {
        accS += __shfl_down_sync(0xffffffffu, accS, off);
        #pragma unroll
        for (int d = 0; d < 16; d++) {
            accM[d] += __shfl_down_sync(0xffffffffu, accM[d], off);
            accQ[d] += __shfl_down_sync(0xffffffffu, accQ[d], off);
        }
    }
    int w = tid >> 5;
    if ((tid & 31) == 0) {
        #pragma unroll
        for (int d = 0; d < 16; d++) { red[d][w] = accM[d]; red[16 + d][w] = accQ[d]; }
        red[32][w] = accS;
    }
    __syncthreads();
    if (tid < 33) {
        float t = 0.0f;
        #pragma unroll
        for (int q = 0; q < 4; q++) t += red[tid][q];
        tot[tid] = t;
    }
    __syncthreads();
    if (tid < 16) {
        float coeff = fmaxf(tot[32], 1e-8f);
        float q     = tot[32] / coeff;
        float mi    = tot[tid] / coeff;
        float sg    = fmaxf(tot[16 + tid] / coeff - (2.0f - q) * mi * mi, 1e-8f);
        g_miu4[bj * 16 + tid] = mi;
        g_isig[bj * 16 + tid] = 1.0f / sg;
        float ls = logf(sg);
        #pragma unroll
        for (int off = 8; off; off >>= 1) ls += __shfl_down_sync(0x0000ffffu, ls, off, 16);
        if (tid == 0) {
            g_lsum[bj] = ls;
            float cost = coeff * (16.0f * beta_u[j] + 0.5f * ls);
            float z = lam * (beta_a[j] - cost);
            g_aout4[bj] = 1.0f / (1.0f + expf(-z));
        }
    }
}

// ---------------------------------------------------------------------------
// Tiled E-step (L2/L3): one block per (b, B_). R writes now coalesced
// (natural [b][i][j] order, consecutive j across threads).
// ---------------------------------------------------------------------------
template <int L>
__global__ void __launch_bounds__(256) k_estep_t(const float* __restrict__ Wt) {
    using G = Cfg<L>;
    extern __shared__ float sm[];
    float* s   = sm;
    float* sMp = sm + G::KK * G::NJ;
    float* sW  = sMp + G::KK * G::OHW * 17;

    int blk = blockIdx.x;
    int B_  = blk & 31;
    int b   = blk >> 5;
    int tid = threadIdx.x;

    for (int idx = tid; idx < G::KK * G::OHW * 16; idx += 256) {
        int d  = idx & 15;
        int p  = (idx >> 4) % G::OHW;
        int kk = idx / (16 * G::OHW);
        sMp[(kk * G::OHW + p) * 17 + d] =
            g_Mpatch[((size_t)(b * G::OHW + p) * G::NI + B_ * G::KK + kk) * 16 + d];
    }
    for (int idx = tid; idx < G::KK * G::C * 16; idx += 256) {
        int d  = idx & 15;
        int c  = (idx >> 4) % G::C;
        int kk = idx / (16 * G::C);
        sW[(kk * G::C + c) * 17 + d] = Wt[((B_ * G::KK + kk) * G::C + c) * 16 + d];
    }
    __syncthreads();

    const float* miu  = Cfg<L>::miu();
    const float* aout = Cfg<L>::aout();
    float lmax[G::KK];
    #pragma unroll
    for (int kk = 0; kk < G::KK; kk++) lmax[kk] = -3.0e38f;

    for (int j = tid; j < G::NJ; j += 256) {
        int c = j / G::OHW, p = j % G::OHW;
        int bj = b * G::NJ + j;
        float mu[16], iv[16];
        const float4* mp4 = reinterpret_cast<const float4*>(miu + bj * 16);
        const float4* ip4 = reinterpret_cast<const float4*>(g_isig + bj * 16);
        #pragma unroll
        for (int q4 = 0; q4 < 4; q4++) {
            float4 m = mp4[q4], v = ip4[q4];
            mu[q4 * 4 + 0] = m.x; mu[q4 * 4 + 1] = m.y; mu[q4 * 4 + 2] = m.z; mu[q4 * 4 + 3] = m.w;
            iv[q4 * 4 + 0] = v.x; iv[q4 * 4 + 1] = v.y; iv[q4 * 4 + 2] = v.z; iv[q4 * 4 + 3] = v.w;
        }
        float base = g_lsum[bj] + 16.0f * LN2PI;
        float aj   = aout[bj];
        #pragma unroll
        for (int kk = 0; kk < G::KK; kk++) {
            const float* Wp = sW + (kk * G::C + c) * 17;
            const float* Mp = sMp + (kk * G::OHW + p) * 17;
            float acc = base;
            #pragma unroll
            for (int r0 = 0; r0 < 4; r0++)
                #pragma unroll
                for (int cc = 0; cc < 4; cc++) {
                    float v = 0.0f;
                    #pragma unroll
                    for (int t = 0; t < 4; t++) v = fmaf(Wp[r0 * 4 + t], Mp[t * 4 + cc], v);
                    int e = r0 * 4 + cc;
                    float dd = v - mu[e];
                    acc = fmaf(dd * dd, iv[e], acc);
                }
            float sj = aj * (-0.5f * acc);
            s[kk * G::NJ + j] = sj;
            lmax[kk] = fmaxf(lmax[kk], sj);
        }
    }

    __shared__ float redm[G::KK][8];
    __shared__ float reds[G::KK][8];
    #pragma unroll
    for (int kk = 0; kk < G::KK; kk++)
        #pragma unroll
        for (int off = 16; off; off >>= 1)
            lmax[kk] = fmaxf(lmax[kk], __shfl_down_sync(0xffffffffu, lmax[kk], off));
    int w = tid >> 5;
    if ((tid & 31) == 0)
        #pragma unroll
        for (int kk = 0; kk < G::KK; kk++) redm[kk][w] = lmax[kk];
    __syncthreads();
    float m[G::KK];
    #pragma unroll
    for (int kk = 0; kk < G::KK; kk++) {
        float mm = redm[kk][0];
        #pragma unroll
        for (int q = 1; q < 8; q++) mm = fmaxf(mm, redm[kk][q]);
        m[kk] = mm;
    }

    float lsm[G::KK];
    #pragma unroll
    for (int kk = 0; kk < G::KK; kk++) lsm[kk] = 0.0f;
    for (int j = tid; j < G::NJ; j += 256) {
        #pragma unroll
        for (int kk = 0; kk < G::KK; kk++) {
            float e = expf(s[kk * G::NJ + j] - m[kk]);
            s[kk * G::NJ + j] = e;
            lsm[kk] += e;
        }
    }
    #pragma unroll
    for (int kk = 0; kk < G::KK; kk++)
        #pragma unroll
        for (int off = 16; off; off >>= 1)
            lsm[kk] += __shfl_down_sync(0xffffffffu, lsm[kk], off);
    if ((tid & 31) == 0)
        #pragma unroll
        for (int kk = 0; kk < G::KK; kk++) reds[kk][w] = lsm[kk];
    __syncthreads();
    float inv[G::KK];
    #pragma unroll
    for (int kk = 0; kk < G::KK; kk++) {
        float t = 0.0f;
        #pragma unroll
        for (int q = 0; q < 8; q++) t += reds[kk][q];
        inv[kk] = 1.0f / t;
    }

    for (int j = tid; j < G::NJ; j += 256) {
        #pragma unroll
        for (int kk = 0; kk < G::KK; kk++)
            g_R[((size_t)(b * G::NI + B_ * G::KK + kk)) * G::NJ + j] = s[kk * G::NJ + j] * inv[kk];
    }
}

// ---------------------------------------------------------------------------
// E-step L4: one warp per (b,i)
// ---------------------------------------------------------------------------
__global__ void __launch_bounds__(256) k_estep4(const float* __restrict__ Wt) {
    int g    = blockIdx.x * 8 + (threadIdx.x >> 5);
    int lane = threadIdx.x & 31;
    int i = g & 511;
    int b = g >> 9;
    int B_ = i >> 4, kk = i & 15;

    float Mv[16];
    const float4* Mp4 = reinterpret_cast<const float4*>(g_Mpatch + ((size_t)(b * 512 + i)) * 16);
    #pragma unroll
    for (int q4 = 0; q4 < 4; q4++) {
        float4 mv = Mp4[q4];
        Mv[q4 * 4 + 0] = mv.x; Mv[q4 * 4 + 1] = mv.y; Mv[q4 * 4 + 2] = mv.z; Mv[q4 * 4 + 3] = mv.w;
    }
    float cx = (float)(kk >> 2) * 0.25f;
    float cy = (float)(kk & 3) * 0.25f;

    float sj = -3.0e38f;
    if (lane < 5) {
        int bj = b * 5 + lane;
        const float4* W4 = reinterpret_cast<const float4*>(Wt + (B_ * 5 + lane) * 16);
        float Wv[16];
        #pragma unroll
        for (int q4 = 0; q4 < 4; q4++) {
            float4 wv = W4[q4];
            Wv[q4 * 4 + 0] = wv.x; Wv[q4 * 4 + 1] = wv.y; Wv[q4 * 4 + 2] = wv.z; Wv[q4 * 4 + 3] = wv.w;
        }
        const float* mu = g_miu4 + bj * 16;
        const float* iv = g_isig + bj * 16;
        float acc = g_lsum[bj] + 16.0f * LN2PI;
        #pragma unroll
        for (int r0 = 0; r0 < 4; r0++)
            #pragma unroll
            for (int cc = 0; cc < 4; cc++) {
                float v = 0.0f;
                #pragma unroll
                for (int t = 0; t < 4; t++) v = fmaf(Wv[r0 * 4 + t], Mv[t * 4 + cc], v);
                int e = r0 * 4 + cc;
                if (e == 0) v += cx;
                if (e == 1) v += cy;
                float dd = v - mu[e];
                acc = fmaf(dd * dd, iv[e], acc);
            }
        sj = g_aout4[bj] * (-0.5f * acc);
    }
    float mm = sj;
    #pragma unroll
    for (int off = 16; off; off >>= 1) mm = fmaxf(mm, __shfl_xor_sync(0xffffffffu, mm, off));
    float e = (lane < 5) ? expf(sj - mm) : 0.0f;
    float ssum = e;
    #pragma unroll
    for (int off = 16; off; off >>= 1) ssum += __shfl_xor_sync(0xffffffffu, ssum, off);
    if (lane < 5) g_R[((size_t)(b * 512 + i)) * 5 + lane] = e / ssum;
}

__global__ void k_final(float* __restrict__ out) {
    int idx = threadIdx.x;
    if (idx < 80) out[idx] = g_aout4[idx];
}

// ---------------------------------------------------------------------------
// Host. k_mstep_t<2> stays at global launch #4 for the ncu window.
// ---------------------------------------------------------------------------
template <int L>
static void run_layer(const float* W, const float* ba, const float* bu) {
    using G = Cfg<L>;
    const int esmem = (G::KK * G::NJ + G::KK * G::OHW * 17 + G::KK * G::C * 17) * 4;
    cudaFuncSetAttribute(k_estep_t<L>, cudaFuncAttributeMaxDynamicSharedMemorySize, esmem);

    k_patch<L><<<(16 * G::OHW * G::NI * 16 + 255) / 256, 256>>>();
    for (int t = 0; t < 3; t++) {
        float lam = 0.01f * (1.0f - powf(0.95f, (float)(t + 1)));
        k_mstep_t<L><<<16 * (G::C / 4) * (G::OHW / 4), 256>>>(ba, bu, W, lam, t == 0 ? 1 : 0);
        if (t < 2) k_estep_t<L><<<16 * 32, 256, esmem>>>(W);
    }
}

static void run_layer4(const float* W, const float* ba, const float* bu) {
    k_patch<4><<<(16 * 512 * 16 + 255) / 256, 256>>>();
    for (int t = 0; t < 3; t++) {
        float lam = 0.01f * (1.0f - powf(0.95f, (float)(t + 1)));
        k_mstep4<<<16 * 5, 128>>>(ba, bu, W, lam, t == 0 ? 1 : 0);
        if (t < 2) k_estep4<<<16 * 512 / 8, 256>>>(W);
    }
}

extern "C" void kernel_launch(void* const* d_in, const int* in_sizes, int n_in,
                              void* d_out, int out_size) {
    const float* x      = (const float*)d_in[0];
    const float* conv_w = (const float*)d_in[1];
    const float* conv_b = (const float*)d_in[2];
    const float* pose_w = (const float*)d_in[3];
    const float* pose_b = (const float*)d_in[4];
    const float* act_w  = (const float*)d_in[5];
    const float* act_b  = (const float*)d_in[6];
    const float* W2     = (const float*)d_in[7];
    const float* ba2    = (const float*)d_in[8];
    const float* bu2    = (const float*)d_in[9];
    const float* W3     = (const float*)d_in[10];
    const float* ba3    = (const float*)d_in[11];
    const float* bu3    = (const float*)d_in[12];
    const float* W4     = (const float*)d_in[13];
    const float* ba4    = (const float*)d_in[14];
    const float* bu4    = (const float*)d_in[15];

    // launch #1..#3: stem, primary, patch<2>   -> launch #4 = k_mstep_t<2>
    k_stem<<<(16 * 32 * 196 + 255) / 256, 256>>>(x, conv_w, conv_b);
    k_primary<<<(16 * 544 * 196 + 255) / 256, 256>>>(pose_w, pose_b, act_w, act_b);

    run_layer<2>(W2, ba2, bu2);
    run_layer<3>(W3, ba3, bu3);
    run_layer4(W4, ba4, bu4);

    k_final<<<1, 128>>>((float*)d_out);
}

// round 15
// speedup vs baseline: 2.1319x; 1.2351x over previous
#include <cuda_runtime.h>
#include <math.h>

#define LN2PI 1.8378770664093453f

// ---------------------------------------------------------------------------
// Device scratch
// ---------------------------------------------------------------------------
__device__ __align__(128) float g_fea[16 * 32 * 196];        // [b][c][s]
__device__ __align__(128) float g_M1[16 * 196 * 512];        // [b][s][u]  channel-fastest
__device__ __align__(128) float g_a1[16 * 196 * 32];         // [b][s][B]
__device__ __align__(128) float g_Mpatch[16 * 36 * 288 * 16];// [b][p][i][16]
__device__ __align__(128) float g_Apatch[16 * 36 * 288];     // [b][p][i]
__device__ __align__(128) float g_R[16 * 288 * 1152];        // [b][i][j]  natural order
__device__ __align__(128) float g_miu2[16 * 1152 * 16];      // [bj][d]
__device__ __align__(128) float g_miuT2[16 * 36 * 16 * 32];  // [b][p][d][c]
__device__ __align__(128) float g_aout2[16 * 1152];
__device__ __align__(128) float g_miu3[16 * 512 * 16];
__device__ __align__(128) float g_miuT3[16 * 16 * 16 * 32];  // [b][p][d][c]
__device__ __align__(128) float g_aout3[16 * 512];
__device__ __align__(128) float g_miu4[16 * 5 * 16];
__device__ __align__(128) float g_aout4[16 * 5];
__device__ __align__(128) float g_isig[16 * 1152 * 16];
__device__ __align__(128) float g_lsum[16 * 1152];

// ---------------------------------------------------------------------------
// Stem conv 5x5 stride 2 + relu
// ---------------------------------------------------------------------------
__global__ void k_stem(const float* __restrict__ x,
                       const float* __restrict__ cw,
                       const float* __restrict__ cb) {
    int idx = blockIdx.x * blockDim.x + threadIdx.x;
    if (idx >= 16 * 32 * 196) return;
    int xx = idx % 14;
    int y  = (idx / 14) % 14;
    int o  = (idx / 196) % 32;
    int b  = idx / (196 * 32);
    float acc = cb[o];
    #pragma unroll
    for (int ci = 0; ci < 2; ci++)
        #pragma unroll
        for (int ky = 0; ky < 5; ky++)
            #pragma unroll
            for (int kx = 0; kx < 5; kx++)
                acc = fmaf(x[((b * 2 + ci) * 32 + 2 * y + ky) * 32 + 2 * xx + kx],
                           cw[((o * 2 + ci) * 5 + ky) * 5 + kx], acc);
    g_fea[idx] = fmaxf(acc, 0.0f);
}

// ---------------------------------------------------------------------------
// Primary caps
// ---------------------------------------------------------------------------
__global__ void k_primary(const float* __restrict__ pw, const float* __restrict__ pb,
                          const float* __restrict__ aw, const float* __restrict__ ab) {
    int idx = blockIdx.x * blockDim.x + threadIdx.x;
    if (idx >= 16 * 544 * 196) return;
    int s = idx % 196;
    int o = (idx / 196) % 544;
    int b = idx / (196 * 544);
    const float* f = &g_fea[(b * 32) * 196 + s];
    if (o < 512) {
        float acc = pb[o];
        #pragma unroll
        for (int c = 0; c < 32; c++) acc = fmaf(f[c * 196], pw[o * 32 + c], acc);
        g_M1[(b * 196 + s) * 512 + o] = acc;
    } else {
        int oa = o - 512;
        float acc = ab[oa];
        #pragma unroll
        for (int c = 0; c < 32; c++) acc = fmaf(f[c * 196], aw[oa * 32 + c], acc);
        g_a1[(b * 196 + s) * 32 + oa] = 1.0f / (1.0f + expf(-acc));
    }
}

// ---------------------------------------------------------------------------
// Per-layer config traits
// ---------------------------------------------------------------------------
template <int L> struct Cfg;

template <> struct Cfg<2> {
    static constexpr int C = 32, K = 3, S = 2, OW = 6;
    static constexpr int KK = 9, NI = 288, NJ = 1152, OHW = 36;
    __device__ static float Min(int b, int u, int y, int x) {
        return g_M1[(b * 196 + y * 14 + x) * 512 + u];
    }
    __device__ static float Ain(int b, int B_, int y, int x) {
        return g_a1[(b * 196 + y * 14 + x) * 32 + B_];
    }
    __device__ static float* miu()  { return g_miu2; }
    __device__ static float* miuT() { return g_miuT2; }
    __device__ static float* aout() { return g_aout2; }
};
template <> struct Cfg<3> {
    static constexpr int C = 32, K = 3, S = 1, OW = 4;
    static constexpr int KK = 9, NI = 288, NJ = 512, OHW = 16;
    __device__ static float Min(int b, int u, int y, int x) {
        int cp = u & 31, dp = u >> 5;
        return g_miuT2[((b * 36 + y * 6 + x) * 16 + dp) * 32 + cp];
    }
    __device__ static float Ain(int b, int B_, int y, int x) {
        return g_aout2[b * 1152 + B_ * 36 + y * 6 + x];
    }
    __device__ static float* miu()  { return g_miu3; }
    __device__ static float* miuT() { return g_miuT3; }
    __device__ static float* aout() { return g_aout3; }
};
template <> struct Cfg<4> {
    static constexpr int C = 5, K = 4, S = 1, OW = 1;
    static constexpr int KK = 16, NI = 512, NJ = 5, OHW = 1;
    __device__ static float Min(int b, int u, int y, int x) {
        int cp = u & 31, dp = u >> 5;
        return g_miuT3[((b * 16 + y * 4 + x) * 16 + dp) * 32 + cp];
    }
    __device__ static float Ain(int b, int B_, int y, int x) {
        return g_aout3[b * 512 + B_ * 16 + y * 4 + x];
    }
    __device__ static float* miu()  { return g_miu4; }
    __device__ static float* miuT() { return g_miuT3; } // unused
    __device__ static float* aout() { return g_aout4; }
};

// ---------------------------------------------------------------------------
// Fused patch builder: Mpatch[b][p][i][16] + Apatch[b][p][i]
// ---------------------------------------------------------------------------
template <int L>
__global__ void k_patch() {
    using G = Cfg<L>;
    int idx = blockIdx.x * blockDim.x + threadIdx.x;
    const int total = 16 * G::OHW * G::NI * 16;
    if (idx >= total) return;
    int d  = idx & 15;
    int t  = idx >> 4;
    int i  = t % G::NI;
    int p  = (t / G::NI) % G::OHW;
    int b  = t / (G::NI * G::OHW);
    int B_ = i / G::KK, kk = i % G::KK;
    int y  = kk / G::K + G::S * (p / G::OW);
    int x  = kk % G::K + G::S * (p % G::OW);
    g_Mpatch[idx] = G::Min(b, B_ * 16 + d, y, x);
    if (d == 0) g_Apatch[t] = G::Ain(b, B_, y, x);
}

// ---------------------------------------------------------------------------
// Tiled M-step (L2/L3) with SMEM-staged operands.
// Block = (b, 4c x 4p) tile of 16 j's; lanes: islot = tid>>4, js = tid&15.
// Per 48-i chunk, cooperatively stage Mp[48][4p][16] and W[48][4c][16] into
// smem (20-float row pitch -> the 8 (i x pg) broadcast groups per warp hit
// 8 disjoint bank quads: N=1). Inner loop reads via LDS, leaving only the
// R read + A broadcast on L1TEX. Note W row index (B_*KK+kk) == i.
// ---------------------------------------------------------------------------
template <int L>
__global__ void __launch_bounds__(256) k_mstep_t(const float* __restrict__ beta_a,
                                                 const float* __restrict__ beta_u,
                                                 const float* __restrict__ Wt,
                                                 float lam, int first) {
    using G = Cfg<L>;
    constexpr int PG = G::OHW / 4;
    constexpr int CH = 48;                 // i's per chunk; NI=288 -> 6 chunks
    constexpr int PITCH = 20;              // floats per (i, pg) row (16 + 4 pad)
    __shared__ float sMp[CH * 4 * PITCH];  // [ii][pg][d]
    __shared__ float sW [CH * 4 * PITCH];  // [ii][cg][d]
    __shared__ float stot[8][16][33];

    int blk  = blockIdx.x;
    int pgrp = blk % PG;
    int cgrp = (blk / PG) % (G::C / 4);
    int b    = blk / (PG * (G::C / 4));
    int tid  = threadIdx.x;
    int islot = tid >> 4;
    int js    = tid & 15;
    int cg = js >> 2, pgg = js & 3;
    int c = cgrp * 4 + cg;
    int p = pgrp * 4 + pgg;
    int j = c * G::OHW + p;

    const float invNJ = 1.0f / (float)G::NJ;
    float accS = 0.0f, accM[16], accQ[16];
    #pragma unroll
    for (int d = 0; d < 16; d++) { accM[d] = 0.0f; accQ[d] = 0.0f; }

    const float* Arow = g_Apatch + (size_t)(b * G::OHW + p) * G::NI;
    const float* Rb   = g_R + (size_t)b * G::NI * G::NJ;

    for (int ch = 0; ch < G::NI / CH; ch++) {
        __syncthreads();
        // cooperative stage: 2 float4 per thread per array
        // map u = pg*(CH*4) + ii*4 + q4  -> contiguous 3KB per pg for Mp
        #pragma unroll
        for (int rep = 0; rep < (CH * 16) / 256; rep++) {
            int u  = rep * 256 + tid;
            int q4 = u & 3;
            int ii = (u >> 2) % CH;
            int pg = u / (CH * 4);
            int i  = ch * CH + ii;
            float4 mv = *reinterpret_cast<const float4*>(
                g_Mpatch + ((size_t)(b * G::OHW + pgrp * 4 + pg) * G::NI + i) * 16 + q4 * 4);
            *reinterpret_cast<float4*>(sMp + (ii * 4 + pg) * PITCH + q4 * 4) = mv;
            float4 wv = *reinterpret_cast<const float4*>(
                Wt + ((size_t)i * G::C + cgrp * 4 + pg) * 16 + q4 * 4);
            *reinterpret_cast<float4*>(sW + (ii * 4 + pg) * PITCH + q4 * 4) = wv;
        }
        __syncthreads();
        #pragma unroll
        for (int ii2 = 0; ii2 < CH / 16; ii2++) {
            int ii = ii2 * 16 + islot;
            int i  = ch * CH + ii;
            float r  = first ? invNJ : Rb[(size_t)i * G::NJ + j];
            float ra = r * Arow[i];
            const float4* Mp4 = reinterpret_cast<const float4*>(sMp + (ii * 4 + pgg) * PITCH);
            const float4* W4  = reinterpret_cast<const float4*>(sW  + (ii * 4 + cg ) * PITCH);
            float Mv[16], Wv[16];
            #pragma unroll
            for (int q4 = 0; q4 < 4; q4++) {
                float4 m = Mp4[q4], w = W4[q4];
                Mv[q4 * 4 + 0] = m.x; Mv[q4 * 4 + 1] = m.y; Mv[q4 * 4 + 2] = m.z; Mv[q4 * 4 + 3] = m.w;
                Wv[q4 * 4 + 0] = w.x; Wv[q4 * 4 + 1] = w.y; Wv[q4 * 4 + 2] = w.z; Wv[q4 * 4 + 3] = w.w;
            }
            accS += ra;
            #pragma unroll
            for (int r0 = 0; r0 < 4; r0++)
                #pragma unroll
                for (int cc = 0; cc < 4; cc++) {
                    float v = 0.0f;
                    #pragma unroll
                    for (int t = 0; t < 4; t++) v = fmaf(Wv[r0 * 4 + t], Mv[t * 4 + cc], v);
                    int e = r0 * 4 + cc;
                    accM[e] = fmaf(ra, v, accM[e]);
                    accQ[e] = fmaf(ra * v, v, accQ[e]);
                }
        }
    }

    // combine the two islots within each warp (lane l += lane l+16)
    accS += __shfl_down_sync(0xffffffffu, accS, 16);
    #pragma unroll
    for (int d = 0; d < 16; d++) {
        accM[d] += __shfl_down_sync(0xffffffffu, accM[d], 16);
        accQ[d] += __shfl_down_sync(0xffffffffu, accQ[d], 16);
    }
    __syncthreads();
    int w = tid >> 5, lane = tid & 31;
    if (lane < 16) {
        #pragma unroll
        for (int d = 0; d < 16; d++) { stot[w][lane][d] = accM[d]; stot[w][lane][16 + d] = accQ[d]; }
        stot[w][lane][32] = accS;
    }
    __syncthreads();
    {
        int js2 = tid >> 4, d = tid & 15;
        float sm_ = 0.0f, sq_ = 0.0f, ss_ = 0.0f;
        #pragma unroll
        for (int q = 0; q < 8; q++) {
            sm_ += stot[q][js2][d];
            sq_ += stot[q][js2][16 + d];
            ss_ += stot[q][js2][32];
        }
        int c2 = cgrp * 4 + (js2 >> 2);
        int p2 = pgrp * 4 + (js2 & 3);
        int j2 = c2 * G::OHW + p2;
        int bj = b * G::NJ + j2;
        float coeff = fmaxf(ss_, 1e-8f);
        float q     = ss_ / coeff;
        float mi    = sm_ / coeff;
        float sg    = fmaxf(sq_ / coeff - (2.0f - q) * mi * mi, 1e-8f);
        Cfg<L>::miu()[bj * 16 + d] = mi;
        Cfg<L>::miuT()[((b * G::OHW + p2) * 16 + d) * 32 + c2] = mi;
        g_isig[bj * 16 + d] = 1.0f / sg;
        float ls = logf(sg);
        #pragma unroll
        for (int off = 8; off; off >>= 1) ls += __shfl_down_sync(0xffffffffu, ls, off, 16);
        if (d == 0) {
            g_lsum[bj] = ls;
            int jc = j2 % G::C;
            float cost = coeff * (16.0f * beta_u[jc] + 0.5f * ls);
            float z = lam * (beta_a[jc] - cost);
            Cfg<L>::aout()[bj] = 1.0f / (1.0f + expf(-z));
        }
    }
}

// ---------------------------------------------------------------------------
// L4 M-step (NJ=5, shared W, coords). One block per (b,j).
// ---------------------------------------------------------------------------
__global__ void __launch_bounds__(128) k_mstep4(const float* __restrict__ beta_a,
                                                const float* __restrict__ beta_u,
                                                const float* __restrict__ Wt,
                                                float lam, int first) {
    int bj = blockIdx.x;
    int j  = bj % 5;
    int b  = bj / 5;
    int tid = threadIdx.x;

    float accS = 0.0f, accM[16], accQ[16];
    #pragma unroll
    for (int d = 0; d < 16; d++) { accM[d] = 0.0f; accQ[d] = 0.0f; }

    for (int it = 0; it < 4; it++) {
        int i = it * 128 + tid;
        int B_ = i >> 4, kk = i & 15;
        float r  = first ? 0.2f : g_R[((size_t)(b * 512 + i)) * 5 + j];
        float ra = r * g_Apatch[b * 512 + i];
        const float4* Mp4 = reinterpret_cast<const float4*>(g_Mpatch + ((size_t)(b * 512 + i)) * 16);
        const float4* W4  = reinterpret_cast<const float4*>(Wt + (B_ * 5 + j) * 16);
        float Mv[16], Wv[16];
        #pragma unroll
        for (int q4 = 0; q4 < 4; q4++) {
            float4 m = Mp4[q4], w = W4[q4];
            Mv[q4 * 4 + 0] = m.x; Mv[q4 * 4 + 1] = m.y; Mv[q4 * 4 + 2] = m.z; Mv[q4 * 4 + 3] = m.w;
            Wv[q4 * 4 + 0] = w.x; Wv[q4 * 4 + 1] = w.y; Wv[q4 * 4 + 2] = w.z; Wv[q4 * 4 + 3] = w.w;
        }
        float cx = (float)(kk >> 2) * 0.25f;
        float cy = (float)(kk & 3) * 0.25f;
        accS += ra;
        #pragma unroll
        for (int r0 = 0; r0 < 4; r0++)
            #pragma unroll
            for (int cc = 0; cc < 4; cc++) {
                float v = 0.0f;
                #pragma unroll
                for (int t = 0; t < 4; t++) v = fmaf(Wv[r0 * 4 + t], Mv[t * 4 + cc], v);
                int e = r0 * 4 + cc;
                if (e == 0) v += cx;
                if (e == 1) v += cy;
                accM[e] = fmaf(ra, v, accM[e]);
                accQ[e] = fmaf(ra * v, v, accQ[e]);
            }
    }

    __shared__ float red[33][4];
    __shared__ float tot[33];
    #pragma unroll
    for (int off = 16; off; off >>= 1) {
        accS += __shfl_down_sync(0xffffffffu, accS, off);
        #pragma unroll
        for (int d = 0; d < 16; d++) {
            accM[d] += __shfl_down_sync(0xffffffffu, accM[d], off);
            accQ[d] += __shfl_down_sync(0xffffffffu, accQ[d], off);
        }
    }
    int w = tid >> 5;
    if ((tid & 31) == 0) {
        #pragma unroll
        for (int d = 0; d < 16; d++) { red[d][w] = accM[d]; red[16 + d][w] = accQ[d]; }
        red[32][w] = accS;
    }
    __syncthreads();
    if (tid < 33) {
        float t = 0.0f;
        #pragma unroll
        for (int q = 0; q < 4; q++) t += red[tid][q];
        tot[tid] = t;
    }
    __syncthreads();
    if (tid < 16) {
        float coeff = fmaxf(tot[32], 1e-8f);
        float q     = tot[32] / coeff;
        float mi    = tot[tid] / coeff;
        float sg    = fmaxf(tot[16 + tid] / coeff - (2.0f - q) * mi * mi, 1e-8f);
        g_miu4[bj * 16 + tid] = mi;
        g_isig[bj * 16 + tid] = 1.0f / sg;
        float ls = logf(sg);
        #pragma unroll
        for (int off = 8; off; off >>= 1) ls += __shfl_down_sync(0x0000ffffu, ls, off, 16);
        if (tid == 0) {
            g_lsum[bj] = ls;
            float cost = coeff * (16.0f * beta_u[j] + 0.5f * ls);
            float z = lam * (beta_a[j] - cost);
            g_aout4[bj] = 1.0f / (1.0f + expf(-z));
        }
    }
}

// ---------------------------------------------------------------------------
// Tiled E-step (L2/L3): one block per (b, B_). R writes coalesced.
// ---------------------------------------------------------------------------
template <int L>
__global__ void __launch_bounds__(256) k_estep_t(const float* __restrict__ Wt) {
    using G = Cfg<L>;
    extern __shared__ float sm[];
    float* s   = sm;
    float* sMp = sm + G::KK * G::NJ;
    float* sW  = sMp + G::KK * G::OHW * 17;

    int blk = blockIdx.x;
    int B_  = blk & 31;
    int b   = blk >> 5;
    int tid = threadIdx.x;

    for (int idx = tid; idx < G::KK * G::OHW * 16; idx += 256) {
        int d  = idx & 15;
        int p  = (idx >> 4) % G::OHW;
        int kk = idx / (16 * G::OHW);
        sMp[(kk * G::OHW + p) * 17 + d] =
            g_Mpatch[((size_t)(b * G::OHW + p) * G::NI + B_ * G::KK + kk) * 16 + d];
    }
    for (int idx = tid; idx < G::KK * G::C * 16; idx += 256) {
        int d  = idx & 15;
        int c  = (idx >> 4) % G::C;
        int kk = idx / (16 * G::C);
        sW[(kk * G::C + c) * 17 + d] = Wt[((B_ * G::KK + kk) * G::C + c) * 16 + d];
    }
    __syncthreads();

    const float* miu  = Cfg<L>::miu();
    const float* aout = Cfg<L>::aout();
    float lmax[G::KK];
    #pragma unroll
    for (int kk = 0; kk < G::KK; kk++) lmax[kk] = -3.0e38f;

    for (int j = tid; j < G::NJ; j += 256) {
        int c = j / G::OHW, p = j % G::OHW;
        int bj = b * G::NJ + j;
        float mu[16], iv[16];
        const float4* mp4 = reinterpret_cast<const float4*>(miu + bj * 16);
        const float4* ip4 = reinterpret_cast<const float4*>(g_isig + bj * 16);
        #pragma unroll
        for (int q4 = 0; q4 < 4; q4++) {
            float4 m = mp4[q4], v = ip4[q4];
            mu[q4 * 4 + 0] = m.x; mu[q4 * 4 + 1] = m.y; mu[q4 * 4 + 2] = m.z; mu[q4 * 4 + 3] = m.w;
            iv[q4 * 4 + 0] = v.x; iv[q4 * 4 + 1] = v.y; iv[q4 * 4 + 2] = v.z; iv[q4 * 4 + 3] = v.w;
        }
        float base = g_lsum[bj] + 16.0f * LN2PI;
        float aj   = aout[bj];
        #pragma unroll
        for (int kk = 0; kk < G::KK; kk++) {
            const float* Wp = sW + (kk * G::C + c) * 17;
            const float* Mp = sMp + (kk * G::OHW + p) * 17;
            float acc = base;
            #pragma unroll
            for (int r0 = 0; r0 < 4; r0++)
                #pragma unroll
                for (int cc = 0; cc < 4; cc++) {
                    float v = 0.0f;
                    #pragma unroll
                    for (int t = 0; t < 4; t++) v = fmaf(Wp[r0 * 4 + t], Mp[t * 4 + cc], v);
                    int e = r0 * 4 + cc;
                    float dd = v - mu[e];
                    acc = fmaf(dd * dd, iv[e], acc);
                }
            float sj = aj * (-0.5f * acc);
            s[kk * G::NJ + j] = sj;
            lmax[kk] = fmaxf(lmax[kk], sj);
        }
    }

    __shared__ float redm[G::KK][8];
    __shared__ float reds[G::KK][8];
    #pragma unroll
    for (int kk = 0; kk < G::KK; kk++)
        #pragma unroll
        for (int off = 16; off; off >>= 1)
            lmax[kk] = fmaxf(lmax[kk], __shfl_down_sync(0xffffffffu, lmax[kk], off));
    int w = tid >> 5;
    if ((tid & 31) == 0)
        #pragma unroll
        for (int kk = 0; kk < G::KK; kk++) redm[kk][w] = lmax[kk];
    __syncthreads();
    float m[G::KK];
    #pragma unroll
    for (int kk = 0; kk < G::KK; kk++) {
        float mm = redm[kk][0];
        #pragma unroll
        for (int q = 1; q < 8; q++) mm = fmaxf(mm, redm[kk][q]);
        m[kk] = mm;
    }

    float lsm[G::KK];
    #pragma unroll
    for (int kk = 0; kk < G::KK; kk++) lsm[kk] = 0.0f;
    for (int j = tid; j < G::NJ; j += 256) {
        #pragma unroll
        for (int kk = 0; kk < G::KK; kk++) {
            float e = expf(s[kk * G::NJ + j] - m[kk]);
            s[kk * G::NJ + j] = e;
            lsm[kk] += e;
        }
    }
    #pragma unroll
    for (int kk = 0; kk < G::KK; kk++)
        #pragma unroll
        for (int off = 16; off; off >>= 1)
            lsm[kk] += __shfl_down_sync(0xffffffffu, lsm[kk], off);
    if ((tid & 31) == 0)
        #pragma unroll
        for (int kk = 0; kk < G::KK; kk++) reds[kk][w] = lsm[kk];
    __syncthreads();
    float inv[G::KK];
    #pragma unroll
    for (int kk = 0; kk < G::KK; kk++) {
        float t = 0.0f;
        #pragma unroll
        for (int q = 0; q < 8; q++) t += reds[kk][q];
        inv[kk] = 1.0f / t;
    }

    for (int j = tid; j < G::NJ; j += 256) {
        #pragma unroll
        for (int kk = 0; kk < G::KK; kk++)
            g_R[((size_t)(b * G::NI + B_ * G::KK + kk)) * G::NJ + j] = s[kk * G::NJ + j] * inv[kk];
    }
}

// ---------------------------------------------------------------------------
// E-step L4: one warp per (b,i)
// ---------------------------------------------------------------------------
__global__ void __launch_bounds__(256) k_estep4(const float* __restrict__ Wt) {
    int g    = blockIdx.x * 8 + (threadIdx.x >> 5);
    int lane = threadIdx.x & 31;
    int i = g & 511;
    int b = g >> 9;
    int B_ = i >> 4, kk = i & 15;

    float Mv[16];
    const float4* Mp4 = reinterpret_cast<const float4*>(g_Mpatch + ((size_t)(b * 512 + i)) * 16);
    #pragma unroll
    for (int q4 = 0; q4 < 4; q4++) {
        float4 mv = Mp4[q4];
        Mv[q4 * 4 + 0] = mv.x; Mv[q4 * 4 + 1] = mv.y; Mv[q4 * 4 + 2] = mv.z; Mv[q4 * 4 + 3] = mv.w;
    }
    float cx = (float)(kk >> 2) * 0.25f;
    float cy = (float)(kk & 3) * 0.25f;

    float sj = -3.0e38f;
    if (lane < 5) {
        int bj = b * 5 + lane;
        const float4* W4 = reinterpret_cast<const float4*>(Wt + (B_ * 5 + lane) * 16);
        float Wv[16];
        #pragma unroll
        for (int q4 = 0; q4 < 4; q4++) {
            float4 wv = W4[q4];
            Wv[q4 * 4 + 0] = wv.x; Wv[q4 * 4 + 1] = wv.y; Wv[q4 * 4 + 2] = wv.z; Wv[q4 * 4 + 3] = wv.w;
        }
        const float* mu = g_miu4 + bj * 16;
        const float* iv = g_isig + bj * 16;
        float acc = g_lsum[bj] + 16.0f * LN2PI;
        #pragma unroll
        for (int r0 = 0; r0 < 4; r0++)
            #pragma unroll
            for (int cc = 0; cc < 4; cc++) {
                float v = 0.0f;
                #pragma unroll
                for (int t = 0; t < 4; t++) v = fmaf(Wv[r0 * 4 + t], Mv[t * 4 + cc], v);
                int e = r0 * 4 + cc;
                if (e == 0) v += cx;
                if (e == 1) v += cy;
                float dd = v - mu[e];
                acc = fmaf(dd * dd, iv[e], acc);
            }
        sj = g_aout4[bj] * (-0.5f * acc);
    }
    float mm = sj;
    #pragma unroll
    for (int off = 16; off; off >>= 1) mm = fmaxf(mm, __shfl_xor_sync(0xffffffffu, mm, off));
    float e = (lane < 5) ? expf(sj - mm) : 0.0f;
    float ssum = e;
    #pragma unroll
    for (int off = 16; off; off >>= 1) ssum += __shfl_xor_sync(0xffffffffu, ssum, off);
    if (lane < 5) g_R[((size_t)(b * 512 + i)) * 5 + lane] = e / ssum;
}

__global__ void k_final(float* __restrict__ out) {
    int idx = threadIdx.x;
    if (idx < 80) out[idx] = g_aout4[idx];
}

// ---------------------------------------------------------------------------
// Host. k_mstep_t<2> stays at global launch #4 for the ncu window.
// ---------------------------------------------------------------------------
template <int L>
static void run_layer(const float* W, const float* ba, const float* bu) {
    using G = Cfg<L>;
    const int esmem = (G::KK * G::NJ + G::KK * G::OHW * 17 + G::KK * G::C * 17) * 4;
    cudaFuncSetAttribute(k_estep_t<L>, cudaFuncAttributeMaxDynamicSharedMemorySize, esmem);

    k_patch<L><<<(16 * G::OHW * G::NI * 16 + 255) / 256, 256>>>();
    for (int t = 0; t < 3; t++) {
        float lam = 0.01f * (1.0f - powf(0.95f, (float)(t + 1)));
        k_mstep_t<L><<<16 * (G::C / 4) * (G::OHW / 4), 256>>>(ba, bu, W, lam, t == 0 ? 1 : 0);
        if (t < 2) k_estep_t<L><<<16 * 32, 256, esmem>>>(W);
    }
}

static void run_layer4(const float* W, const float* ba, const float* bu) {
    k_patch<4><<<(16 * 512 * 16 + 255) / 256, 256>>>();
    for (int t = 0; t < 3; t++) {
        float lam = 0.01f * (1.0f - powf(0.95f, (float)(t + 1)));
        k_mstep4<<<16 * 5, 128>>>(ba, bu, W, lam, t == 0 ? 1 : 0);
        if (t < 2) k_estep4<<<16 * 512 / 8, 256>>>(W);
    }
}

extern "C" void kernel_launch(void* const* d_in, const int* in_sizes, int n_in,
                              void* d_out, int out_size) {
    const float* x      = (const float*)d_in[0];
    const float* conv_w = (const float*)d_in[1];
    const float* conv_b = (const float*)d_in[2];
    const float* pose_w = (const float*)d_in[3];
    const float* pose_b = (const float*)d_in[4];
    const float* act_w  = (const float*)d_in[5];
    const float* act_b  = (const float*)d_in[6];
    const float* W2     = (const float*)d_in[7];
    const float* ba2    = (const float*)d_in[8];
    const float* bu2    = (const float*)d_in[9];
    const float* W3     = (const float*)d_in[10];
    const float* ba3    = (const float*)d_in[11];
    const float* bu3    = (const float*)d_in[12];
    const float* W4     = (const float*)d_in[13];
    const float* ba4    = (const float*)d_in[14];
    const float* bu4    = (const float*)d_in[15];

    // launch #1..#3: stem, primary, patch<2>   -> launch #4 = k_mstep_t<2>
    k_stem<<<(16 * 32 * 196 + 255) / 256, 256>>>(x, conv_w, conv_b);
    k_primary<<<(16 * 544 * 196 + 255) / 256, 256>>>(pose_w, pose_b, act_w, act_b);

    run_layer<2>(W2, ba2, bu2);
    run_layer<3>(W3, ba3, bu3);
    run_layer4(W4, ba4, bu4);

    k_final<<<1, 128>>>((float*)d_out);
}